// round 17
// baseline (speedup 1.0000x reference)
#include <cuda_runtime.h>
#include <cstdint>
#include <math.h>

#define HW 4096
#define NTILES 640
#define NTOT_F 2621440.0f
#define EPS_V 1e-8f
#define LN2F 0.69314718055994530942f

#define SPARSITY_W 0.8f
#define CONC_W     1.5f
#define COORD_W    1.0f
#define BG_W       0.1f

__device__ float g_tile_contrib[NTILES];
__device__ unsigned int g_done = 0;

typedef unsigned long long u64;

__device__ __forceinline__ float fast_tanh(float x) {
    float r; asm("tanh.approx.f32 %0, %1;" : "=f"(r) : "f"(x)); return r;
}
__device__ __forceinline__ float fast_lg2(float x) {
    float r; asm("lg2.approx.f32 %0, %1;" : "=f"(r) : "f"(x)); return r;
}
__device__ __forceinline__ u64 pk(float a, float b) {
    u64 r; asm("mov.b64 %0, {%1, %2};" : "=l"(r) : "f"(a), "f"(b)); return r;
}
__device__ __forceinline__ void upk(float& a, float& b, u64 v) {
    asm("mov.b64 {%0, %1}, %2;" : "=f"(a), "=f"(b) : "l"(v));
}
__device__ __forceinline__ u64 add2(u64 a, u64 b) {
    u64 r; asm("add.rn.f32x2 %0, %1, %2;" : "=l"(r) : "l"(a), "l"(b)); return r;
}
__device__ __forceinline__ u64 sub2(u64 a, u64 b) {
    u64 r; asm("sub.rn.f32x2 %0, %1, %2;" : "=l"(r) : "l"(a), "l"(b)); return r;
}
__device__ __forceinline__ u64 mul2(u64 a, u64 b) {
    u64 r; asm("mul.rn.f32x2 %0, %1, %2;" : "=l"(r) : "l"(a), "l"(b)); return r;
}
__device__ __forceinline__ u64 fma2(u64 a, u64 b, u64 c) {
    u64 r; asm("fma.rn.f32x2 %0, %1, %2, %3;" : "=l"(r) : "l"(a), "l"(b), "l"(c)); return r;
}

// One CTA per tile: 128 threads, 32 px/thread. Elementwise math runs on
// packed f32x2 (add/sub/mul/fma); min/max done scalar on the idle alu pipe.
__global__ __launch_bounds__(128, 5)
void loss_kernel(const ulonglong2* __restrict__ pred,
                 const ulonglong2* __restrict__ tgt,
                 float* __restrict__ out) {
    __shared__ float warp_red[4][12];
    __shared__ bool is_last;

    const int tile = blockIdx.x;
    const ulonglong2* __restrict__ P = pred + (size_t)tile * (HW / 4);
    const ulonglong2* __restrict__ T = tgt  + (size_t)tile * (HW / 4);

    const int tid  = threadIdx.x;          // [0,128)
    const int lane = tid & 31;
    const int wid  = tid >> 5;             // [0,4)

    // elem j = 4*(tid + 128k) + c, k=0..7:
    //   col = ((4*tid)&63) + c  (k-invariant);  row = (tid>>4) + 8k
    const float c0f = (float)((tid * 4) & 63);
    const float y0f = (float)(tid >> 4);

    // front-load everything: 16 x LDG.128 in flight (each = 2 packed pairs)
    ulonglong2 X[8], Tt[8];
    #pragma unroll
    for (int k = 0; k < 8; k++) X[k]  = P[tid + 128 * k];
    #pragma unroll
    for (int k = 0; k < 8; k++) Tt[k] = T[tid + 128 * k];

    const u64 C05 = pk(0.5f, 0.5f);
    const u64 C1  = pk(1.0f, 1.0f);

    // packed accumulators
    u64 focA = 0, foc2 = 0, bgp = 0, plogA = 0, plg2 = 0;
    u64 A01 = 0, A23 = 0, T01 = 0, T23 = 0;        // plain sums per c-slot pair
    u64 wy01 = 0, wy23 = 0, wt01 = 0, wt23 = 0;    // k-weighted sums
    float mxh = -1.f;                              // scalar running max of 2p-1

    #pragma unroll
    for (int k = 0; k < 8; k++) {
        const u64 kk = pk((float)k, (float)k);
        #pragma unroll
        for (int h = 0; h < 2; h++) {              // h=0: c01 pair, h=1: c23 pair
            u64 xp = h ? X[k].y  : X[k].x;
            u64 tp = h ? Tt[k].y : Tt[k].x;

            float x0, x1; upk(x0, x1, xp);
            float h0 = fast_tanh(0.5f * x0);
            float h1 = fast_tanh(0.5f * x1);
            float g0 = fast_lg2(fmaf(0.5f, fabsf(h0), 0.5f));  // log2 sigmoid(|x|)
            float g1 = fast_lg2(fmaf(0.5f, fabsf(h1), 0.5f));
            u64 h2p = pk(h0, h1);
            u64 l2p = pk(g0, g1);
            // scalar min/max on alu pipe (no f32x2 min/max on sm_103a)
            u64 bmax = pk(fmaxf(x0, 0.f), fmaxf(x1, 0.f));
            u64 bmin = pk(fminf(x0, 0.f), fminf(x1, 0.f));
            mxh = fmaxf(mxh, fmaxf(h0, h1));

            u64 pp   = fma2(h2p, C05, C05);        // p = 0.5*h2 + 0.5
            u64 bceA = sub2(bmax, mul2(xp, tp));   // max(x,0) - x*t
            u64 dm   = sub2(tp, pp);
            u64 om2  = mul2(dm, dm);               // (1-p_t)^2
            focA = fma2(om2, bceA, focA);
            foc2 = fma2(om2, l2p,  foc2);
            bgp  = fma2(om2, sub2(C1, tp), bgp);   // p^2 when t==0
            plogA = fma2(pp, bmin, plogA);
            plg2  = fma2(pp, l2p, plg2);
            if (h == 0) {
                A01  = add2(A01, pp);   wy01 = fma2(pp, kk, wy01);
                T01  = add2(T01, tp);   wt01 = fma2(tp, kk, wt01);
            } else {
                A23  = add2(A23, pp);   wy23 = fma2(pp, kk, wy23);
                T23  = add2(T23, tp);   wt23 = fma2(tp, kk, wt23);
            }
        }
    }

    // unpack packed accumulators -> scalar tile statistics
    float a0, a1, a2, a3, b0, b1;
    upk(a0, a1, A01); upk(a2, a3, A23);
    float S   = (a0 + a1) + (a2 + a3);
    float wxp = fmaf(3.f, a3, fmaf(2.f, a2, a1));
    upk(a0, a1, T01); upk(a2, a3, T23);
    float Ts  = (a0 + a1) + (a2 + a3);
    float wxt = fmaf(3.f, a3, fmaf(2.f, a2, a1));
    upk(a0, a1, wy01); upk(a2, a3, wy23);
    float wyp = (a0 + a1) + (a2 + a3);
    upk(a0, a1, wt01); upk(a2, a3, wt23);
    float wyt = (a0 + a1) + (a2 + a3);
    upk(b0, b1, focA);  float fA  = b0 + b1;
    upk(b0, b1, foc2);  float f2v = b0 + b1;
    upk(b0, b1, bgp);   float bg  = b0 + b1;
    upk(b0, b1, plogA); float pA  = b0 + b1;
    upk(b0, b1, plg2);  float p2v = b0 + b1;
    float mx = fmaf(0.5f, mxh, 0.5f);

    float pxs = fmaf(c0f, S,  wxp);
    float pys = fmaf(y0f, S,  8.f * wyp);    // rows step by 8 per k
    float txs = fmaf(c0f, Ts, wxt);
    float tys = fmaf(y0f, Ts, 8.f * wyt);

    // warp butterfly: 11 sums + 1 max
    const unsigned FULL = 0xffffffffu;
    #pragma unroll
    for (int o = 16; o; o >>= 1) {
        S   += __shfl_xor_sync(FULL, S,   o);
        Ts  += __shfl_xor_sync(FULL, Ts,  o);
        pxs += __shfl_xor_sync(FULL, pxs, o);
        pys += __shfl_xor_sync(FULL, pys, o);
        txs += __shfl_xor_sync(FULL, txs, o);
        tys += __shfl_xor_sync(FULL, tys, o);
        fA  += __shfl_xor_sync(FULL, fA,  o);
        f2v += __shfl_xor_sync(FULL, f2v, o);
        bg  += __shfl_xor_sync(FULL, bg,  o);
        pA  += __shfl_xor_sync(FULL, pA,  o);
        p2v += __shfl_xor_sync(FULL, p2v, o);
        mx   = fmaxf(mx, __shfl_xor_sync(FULL, mx, o));
    }
    if (lane == 0) {
        warp_red[wid][0]  = S;    warp_red[wid][1]  = Ts;
        warp_red[wid][2]  = pxs;  warp_red[wid][3]  = pys;
        warp_red[wid][4]  = txs;  warp_red[wid][5]  = tys;
        warp_red[wid][6]  = fA;   warp_red[wid][7]  = f2v;
        warp_red[wid][8]  = bg;   warp_red[wid][9]  = pA;
        warp_red[wid][10] = p2v;  warp_red[wid][11] = mx;
    }
    __syncthreads();

    // cross-warp combine: 4 lanes of warp 0
    if (wid == 0 && lane < 4) {
        float a[12];
        #pragma unroll
        for (int i = 0; i < 12; i++) a[i] = warp_red[lane][i];
        const unsigned M4 = 0x0000000fu;
        #pragma unroll
        for (int o = 2; o; o >>= 1) {
            #pragma unroll
            for (int i = 0; i < 11; i++) a[i] += __shfl_xor_sync(M4, a[i], o);
            a[11] = fmaxf(a[11], __shfl_xor_sync(M4, a[11], o));
        }
        if (lane == 0) {
            float foc  = fmaf(-LN2F, a[7],  a[6]);   // focA - ln2*foc2
            float plog = fmaf( LN2F, a[10], a[9]);   // plogA + ln2*plg2

            float Sp  = a[0] + EPS_V;
            float inv = 1.f / Sp;
            float ent = inv * (a[0] * logf(Sp) - plog);
            float ts  = a[1] + EPS_V;
            float px  = a[2] * inv, py = a[3] * inv;
            float tx  = a[4] / ts,  ty = a[5] / ts;
            float dx  = px - tx,    dy = py - ty;
            float coord = sqrtf(dx * dx + dy * dy);
            float conc  = 1.f - a[11];

            g_tile_contrib[tile] =
                (foc + BG_W * a[8]) * (1.f / NTOT_F) +
                (SPARSITY_W * ent + CONC_W * conc + COORD_W * coord) * (1.f / (float)NTILES);

            __threadfence();
            unsigned r = atomicAdd(&g_done, 1u);
            is_last = (r == NTILES - 1);
        }
    }
    __syncthreads();

    if (is_last) {
        __threadfence();
        float v = 0.f;
        #pragma unroll
        for (int i = 0; i < 5; i++)                // 640 / 128
            v += g_tile_contrib[tid + 128 * i];
        #pragma unroll
        for (int o = 16; o; o >>= 1)
            v += __shfl_xor_sync(FULL, v, o);
        if (lane == 0) warp_red[wid][0] = v;
        __syncthreads();
        if (tid == 0) {
            float s = (warp_red[0][0] + warp_red[1][0])
                    + (warp_red[2][0] + warp_red[3][0]);
            out[0] = s;
            g_done = 0;   // reset for graph replay
        }
    }
}

extern "C" void kernel_launch(void* const* d_in, const int* in_sizes, int n_in,
                              void* d_out, int out_size) {
    const ulonglong2* pred = (const ulonglong2*)d_in[0];
    const ulonglong2* tgt  = (const ulonglong2*)d_in[1];
    float* out = (float*)d_out;
    loss_kernel<<<NTILES, 128>>>(pred, tgt, out);
}